// round 1
// baseline (speedup 1.0000x reference)
#include <cuda_runtime.h>

// Problem constants (fixed by the dataset)
#define N_IMG 4096
#define N_POS 4096
#define N_NEG 4096
#define N_OTH 16384
#define DIM   128

// GEMM tiling
#define BM 128
#define BN 128
#define BK 32
#define PAD 4

// Scratch (device-global: no allocations allowed)
__device__ float g_x2[N_IMG];
__device__ float g_p2[N_POS];
__device__ float g_q2[N_NEG];
__device__ float g_m2[N_OTH];
__device__ float g_Spos[N_IMG];
__device__ float g_Sden[N_IMG];

__device__ __forceinline__ float ex2_approx(float x) {
    float r; asm("ex2.approx.f32 %0, %1;" : "=f"(r) : "f"(x)); return r;
}
__device__ __forceinline__ float sqrt_approx(float x) {
    float r; asm("sqrt.approx.f32 %0, %1;" : "=f"(r) : "f"(x)); return r;
}

// ---------------------------------------------------------------------------
// Kernel 1: squared norms for all rows of all 4 matrices + zero accumulators.
// One warp per row (128 floats = 1 float4 per lane).
// ---------------------------------------------------------------------------
__global__ void prep_kernel(const float* __restrict__ X, const float* __restrict__ P,
                            const float* __restrict__ Q, const float* __restrict__ M) {
    int gwarp = (blockIdx.x * blockDim.x + threadIdx.x) >> 5;
    int lane  = threadIdx.x & 31;
    const float* src; float* dst; int row;
    if (gwarp < N_IMG)                         { row = gwarp;                       src = X + (size_t)row * DIM; dst = g_x2; }
    else if (gwarp < N_IMG + N_POS)            { row = gwarp - N_IMG;               src = P + (size_t)row * DIM; dst = g_p2; }
    else if (gwarp < N_IMG + N_POS + N_NEG)    { row = gwarp - (N_IMG + N_POS);     src = Q + (size_t)row * DIM; dst = g_q2; }
    else                                       { row = gwarp - (N_IMG+N_POS+N_NEG); src = M + (size_t)row * DIM; dst = g_m2; }

    float4 v = ((const float4*)src)[lane];
    float s = v.x * v.x + v.y * v.y + v.z * v.z + v.w * v.w;
    #pragma unroll
    for (int o = 16; o > 0; o >>= 1) s += __shfl_xor_sync(0xFFFFFFFFu, s, o);
    if (lane == 0) {
        dst[row] = s;
        if (gwarp < N_IMG) { g_Spos[gwarp] = 0.0f; g_Sden[gwarp] = 0.0f; }
    }
}

// ---------------------------------------------------------------------------
// Kernel 2: fused tiled GEMM + distance + exp + per-row sum.
// grid = (32 row-tiles, 192 col-tiles). Col-tiles 0..31 -> positives (coef 4,
// accumulate to Spos), 32..63 -> negatives (coef 4, Sden), 64..191 -> other
// (coef 2, Sden). All segments are multiples of BN so every block lies in
// exactly one segment — no bounds checks anywhere.
// ---------------------------------------------------------------------------
__global__ __launch_bounds__(256, 2)
void softnn_main_kernel(const float* __restrict__ X, const float* __restrict__ Pm,
                        const float* __restrict__ Qm, const float* __restrict__ Mm) {
    __shared__ float As[BK][BM + PAD];
    __shared__ float Bs[BK][BN + PAD];

    const int rowTile = blockIdx.x;            // 0..31
    const int cb      = blockIdx.y;            // 0..191

    const float* Y; const float* y2g; float coef; float* target; int colBase;
    if (cb < 32)      { Y = Pm; y2g = g_p2; coef = 4.0f; target = g_Spos; colBase = cb * BN; }
    else if (cb < 64) { Y = Qm; y2g = g_q2; coef = 4.0f; target = g_Sden; colBase = (cb - 32) * BN; }
    else              { Y = Mm; y2g = g_m2; coef = 2.0f; target = g_Sden; colBase = (cb - 64) * BN; }

    const int tid = threadIdx.x;
    const int tx  = tid & 15;          // 0..15 -> 8 columns each
    const int ty  = tid >> 4;          // 0..15 -> 8 rows each
    const int rowBase = rowTile * BM;

    // loader mapping: 256 threads, each loads 4 float4 (one per pass)
    const int lr = tid >> 3;           // 0..31 : row within 32-row pass
    const int lk = (tid & 7) * 4;      // 0,4,...,28 : k offset

    float acc[8][8];
    #pragma unroll
    for (int i = 0; i < 8; i++)
        #pragma unroll
        for (int j = 0; j < 8; j++) acc[i][j] = 0.0f;

    #pragma unroll
    for (int kb = 0; kb < DIM; kb += BK) {
        #pragma unroll
        for (int p = 0; p < 4; ++p) {
            int r = lr + p * 32;
            float4 va = *(const float4*)&X[(size_t)(rowBase + r) * DIM + kb + lk];
            As[lk + 0][r] = va.x; As[lk + 1][r] = va.y;
            As[lk + 2][r] = va.z; As[lk + 3][r] = va.w;
            float4 vb = *(const float4*)&Y[(size_t)(colBase + r) * DIM + kb + lk];
            Bs[lk + 0][r] = vb.x; Bs[lk + 1][r] = vb.y;
            Bs[lk + 2][r] = vb.z; Bs[lk + 3][r] = vb.w;
        }
        __syncthreads();

        #pragma unroll
        for (int k = 0; k < BK; ++k) {
            float a[8], b[8];
            *(float4*)&a[0] = *(const float4*)&As[k][ty * 8];
            *(float4*)&a[4] = *(const float4*)&As[k][ty * 8 + 4];
            *(float4*)&b[0] = *(const float4*)&Bs[k][tx * 8];
            *(float4*)&b[4] = *(const float4*)&Bs[k][tx * 8 + 4];
            #pragma unroll
            for (int i = 0; i < 8; i++)
                #pragma unroll
                for (int j = 0; j < 8; j++)
                    acc[i][j] = fmaf(a[i], b[j], acc[i][j]);
        }
        __syncthreads();
    }

    // Epilogue: d = sqrt(max(x2 + y2 - 2*dot, 0)); accumulate exp(-coef*d)
    float x2v[8], y2v[8];
    #pragma unroll
    for (int i = 0; i < 8; i++) x2v[i] = g_x2[rowBase + ty * 8 + i];
    #pragma unroll
    for (int j = 0; j < 8; j++) y2v[j] = y2g[colBase + tx * 8 + j];

    const float nc = -coef * 1.4426950408889634f;   // -coef * log2(e)
    float rowsum[8];
    #pragma unroll
    for (int i = 0; i < 8; i++) rowsum[i] = 0.0f;

    #pragma unroll
    for (int i = 0; i < 8; i++) {
        #pragma unroll
        for (int j = 0; j < 8; j++) {
            float sq = fmaf(-2.0f, acc[i][j], x2v[i] + y2v[j]);
            sq = fmaxf(sq, 0.0f);
            float d = sqrt_approx(sq);
            rowsum[i] += ex2_approx(nc * d);
        }
    }

    // Reduce across the 16 threads (tx) that share each row; xor masks 1,2,4,8
    // stay inside each 16-lane half-warp (same ty).
    #pragma unroll
    for (int i = 0; i < 8; i++) {
        float s = rowsum[i];
        s += __shfl_xor_sync(0xFFFFFFFFu, s, 1);
        s += __shfl_xor_sync(0xFFFFFFFFu, s, 2);
        s += __shfl_xor_sync(0xFFFFFFFFu, s, 4);
        s += __shfl_xor_sync(0xFFFFFFFFu, s, 8);
        if (tx == 0) atomicAdd(&target[rowBase + ty * 8 + i], s);
    }
}

// ---------------------------------------------------------------------------
// Kernel 3: loss = sum_i ( log(Sden[i]) - log(Spos[i]) )
// ---------------------------------------------------------------------------
__global__ void final_kernel(float* __restrict__ out) {
    __shared__ double sm[256];
    int tid = threadIdx.x;
    double acc = 0.0;
    for (int i = tid; i < N_IMG; i += 256)
        acc += (double)(logf(g_Sden[i]) - logf(g_Spos[i]));
    sm[tid] = acc;
    __syncthreads();
    for (int o = 128; o > 0; o >>= 1) {
        if (tid < o) sm[tid] += sm[tid + o];
        __syncthreads();
    }
    if (tid == 0) out[0] = (float)sm[0];
}

// ---------------------------------------------------------------------------
extern "C" void kernel_launch(void* const* d_in, const int* in_sizes, int n_in,
                              void* d_out, int out_size) {
    const float* X = (const float*)d_in[0];   // image_views    [4096,128]
    const float* P = (const float*)d_in[1];   // positive_views [4096,128]
    const float* Q = (const float*)d_in[2];   // negative_views [4096,128]
    const float* M = (const float*)d_in[3];   // other_embeddings [16384,128]

    // 28672 rows total, one warp per row, 8 warps per block
    prep_kernel<<<(N_IMG + N_POS + N_NEG + N_OTH) / 8, 256>>>(X, P, Q, M);

    dim3 grid(N_IMG / BM, (N_POS + N_NEG + N_OTH) / BN);   // 32 x 192
    softnn_main_kernel<<<grid, 256>>>(X, P, Q, M);

    final_kernel<<<1, 256>>>((float*)d_out);
}